// round 1
// baseline (speedup 1.0000x reference)
#include <cuda_runtime.h>
#include <math.h>

#define NB 4096
#define NT 512
#define OBS 2
#define LAT 4
#define NH 20
#define RNNH 25

// scratch: pred_z[b][t][4]
__device__ float g_pred_z[(size_t)NB * NT * LAT];

static __device__ __forceinline__ float elu_f(float x) {
    return x > 0.f ? x : (expf(x) - 1.f);
}

// ---------------- RNN: one warp per batch element ----------------
__global__ __launch_bounds__(128) void rnn_kernel(
    const float* __restrict__ trajs,   // (B,T,2)
    const float* __restrict__ eps,     // (B,4)
    const float* __restrict__ i2h_w,   // (27,25)
    const float* __restrict__ i2h_b,   // (25)
    const float* __restrict__ h2o_w,   // (25,8)
    const float* __restrict__ h2o_b,   // (8)
    float* __restrict__ out)
{
    int gwarp = (blockIdx.x * blockDim.x + threadIdx.x) >> 5;
    int lane  = threadIdx.x & 31;
    if (gwarp >= NB) return;
    int b = gwarp;
    int j = lane;
    int jc = (j < RNNH) ? j : 0;

    float W[OBS + RNNH];
#pragma unroll
    for (int r = 0; r < OBS + RNNH; r++) W[r] = __ldg(&i2h_w[r * RNNH + jc]);
    float bj = __ldg(&i2h_b[jc]);

    float h = 0.f;
    const float* xb = trajs + (size_t)b * NT * OBS;
    for (int t = NT - 1; t >= 0; --t) {
        float2 x = *(const float2*)(xb + (size_t)t * OBS);
        float acc = fmaf(x.x, W[0], fmaf(x.y, W[1], bj));
#pragma unroll
        for (int k = 0; k < RNNH; k++) {
            float hk = __shfl_sync(0xffffffffu, h, k);
            acc = fmaf(hk, W[2 + k], acc);
        }
        h = (j < RNNH) ? tanhf(acc) : 0.f;
    }

    // out8 = h_last @ h2o_w + h2o_b   (h=0 for lanes >= 25)
    float p[2 * LAT];
#pragma unroll
    for (int i = 0; i < 2 * LAT; i++) p[i] = h * __ldg(&h2o_w[jc * (2 * LAT) + i]);
#pragma unroll
    for (int off = 16; off >= 1; off >>= 1) {
#pragma unroll
        for (int i = 0; i < 2 * LAT; i++)
            p[i] += __shfl_xor_sync(0xffffffffu, p[i], off);
    }

    if (lane == 0) {
        const size_t PX = (size_t)NB * NT * OBS;
        float z0v[LAT];
#pragma unroll
        for (int i = 0; i < LAT; i++) {
            float mean = p[i] + __ldg(&h2o_b[i]);
            float lv   = p[LAT + i] + __ldg(&h2o_b[LAT + i]);
            float z    = __ldg(&eps[b * LAT + i]) * expf(0.5f * lv) + mean;
            z0v[i] = z;
            out[PX + (size_t)b * LAT + i]                     = z;     // z0
            out[PX + (size_t)NB * LAT + (size_t)b * LAT + i]  = mean;  // qz0_mean
            out[PX + 2 * (size_t)NB * LAT + (size_t)b * LAT + i] = lv; // qz0_logvar
        }
        *(float4*)(g_pred_z + (size_t)b * NT * LAT) =
            make_float4(z0v[0], z0v[1], z0v[2], z0v[3]);
    }
}

// ---------------- ODE: 8 lanes per batch element ----------------
__global__ __launch_bounds__(128) void ode_kernel(
    const float* __restrict__ ts,
    const float* __restrict__ f1_w, const float* __restrict__ f1_b,   // (4,20),(20)
    const float* __restrict__ f2_w, const float* __restrict__ f2_b,   // (20,20),(20)
    const float* __restrict__ f3_w, const float* __restrict__ f3_b)   // (20,4),(4)
{
    int tid = blockIdx.x * blockDim.x + threadIdx.x;
    int b = tid >> 3;       // one 8-lane group per batch
    int s = tid & 7;
    if (b >= NB) return;

    // neuron slots: j = s + 8*m, m = 0..2; slot 2 invalid for s >= 4
    int jm[3]; bool vm[3];
#pragma unroll
    for (int m = 0; m < 3; m++) {
        int j = s + 8 * m;
        vm[m] = (j < NH);
        jm[m] = vm[m] ? j : 0;
    }

    float W1[LAT][3], W2[NH][3], W3[3][LAT], b1[3], b2[3], b3[LAT];
#pragma unroll
    for (int m = 0; m < 3; m++) {
#pragma unroll
        for (int i = 0; i < LAT; i++) W1[i][m] = __ldg(&f1_w[i * NH + jm[m]]);
#pragma unroll
        for (int k = 0; k < NH; k++)  W2[k][m] = __ldg(&f2_w[k * NH + jm[m]]);
#pragma unroll
        for (int i = 0; i < LAT; i++) W3[m][i] = __ldg(&f3_w[jm[m] * LAT + i]);
        b1[m] = __ldg(&f1_b[jm[m]]);
        b2[m] = __ldg(&f2_b[jm[m]]);
    }
#pragma unroll
    for (int i = 0; i < LAT; i++) b3[i] = __ldg(&f3_b[i]);

    // f(z) -> kout, replicated across the 8 lanes of the group
    auto feval = [&](const float zin[LAT], float kout[LAT]) {
        float u[3];
#pragma unroll
        for (int m = 0; m < 3; m++) {
            float a = b1[m];
#pragma unroll
            for (int i = 0; i < LAT; i++) a = fmaf(zin[i], W1[i][m], a);
            u[m] = vm[m] ? elu_f(a) : 0.f;
        }
        float a2[3] = { b2[0], b2[1], b2[2] };
#pragma unroll
        for (int k = 0; k < NH; k++) {
            float uk = __shfl_sync(0xffffffffu, u[k >> 3], k & 7, 8);
#pragma unroll
            for (int m = 0; m < 3; m++) a2[m] = fmaf(uk, W2[k][m], a2[m]);
        }
        float u2[3];
#pragma unroll
        for (int m = 0; m < 3; m++) u2[m] = vm[m] ? elu_f(a2[m]) : 0.f;

        float p[LAT] = { 0.f, 0.f, 0.f, 0.f };
#pragma unroll
        for (int m = 0; m < 3; m++)
#pragma unroll
            for (int i = 0; i < LAT; i++) p[i] = fmaf(u2[m], W3[m][i], p[i]);
#pragma unroll
        for (int off = 4; off >= 1; off >>= 1) {
#pragma unroll
            for (int i = 0; i < LAT; i++)
                p[i] += __shfl_xor_sync(0xffffffffu, p[i], off, 8);
        }
#pragma unroll
        for (int i = 0; i < LAT; i++) kout[i] = p[i] + b3[i];
    };

    float z[LAT];
    {
        float4 zz = *(const float4*)(g_pred_z + (size_t)b * NT * LAT);
        z[0] = zz.x; z[1] = zz.y; z[2] = zz.z; z[3] = zz.w;
    }

    for (int t = 0; t < NT - 1; ++t) {
        float dt = __ldg(&ts[t + 1]) - __ldg(&ts[t]);
        float k1[LAT], k2[LAT], k3[LAT], k4[LAT], zt[LAT];
        feval(z, k1);
#pragma unroll
        for (int i = 0; i < LAT; i++) zt[i] = fmaf(0.5f * dt, k1[i], z[i]);
        feval(zt, k2);
#pragma unroll
        for (int i = 0; i < LAT; i++) zt[i] = fmaf(0.5f * dt, k2[i], z[i]);
        feval(zt, k3);
#pragma unroll
        for (int i = 0; i < LAT; i++) zt[i] = fmaf(dt, k3[i], z[i]);
        feval(zt, k4);
        float c = dt * (1.f / 6.f);
#pragma unroll
        for (int i = 0; i < LAT; i++)
            z[i] = fmaf(c, k1[i] + 2.f * k2[i] + 2.f * k3[i] + k4[i], z[i]);
        if (s == 0) {
            *(float4*)(g_pred_z + ((size_t)b * NT + t + 1) * LAT) =
                make_float4(z[0], z[1], z[2], z[3]);
        }
    }
}

// ---------------- Decoder: one thread per (b,t) ----------------
__global__ __launch_bounds__(256) void dec_kernel(
    const float* __restrict__ d1_w, const float* __restrict__ d1_b,  // (4,20),(20)
    const float* __restrict__ d2_w, const float* __restrict__ d2_b,  // (20,2),(2)
    float* __restrict__ out)
{
    int idx = blockIdx.x * blockDim.x + threadIdx.x;
    if (idx >= NB * NT) return;
    float4 z = *(const float4*)(g_pred_z + (size_t)idx * LAT);
    float o0 = __ldg(&d2_b[0]), o1 = __ldg(&d2_b[1]);
#pragma unroll
    for (int j = 0; j < NH; j++) {
        float hh = __ldg(&d1_b[j]);
        hh = fmaf(z.x, __ldg(&d1_w[0 * NH + j]), hh);
        hh = fmaf(z.y, __ldg(&d1_w[1 * NH + j]), hh);
        hh = fmaf(z.z, __ldg(&d1_w[2 * NH + j]), hh);
        hh = fmaf(z.w, __ldg(&d1_w[3 * NH + j]), hh);
        hh = fmaxf(hh, 0.f);
        o0 = fmaf(hh, __ldg(&d2_w[j * 2 + 0]), o0);
        o1 = fmaf(hh, __ldg(&d2_w[j * 2 + 1]), o1);
    }
    ((float2*)out)[idx] = make_float2(o0, o1);
}

extern "C" void kernel_launch(void* const* d_in, const int* in_sizes, int n_in,
                              void* d_out, int out_size)
{
    const float* trajs = (const float*)d_in[0];
    const float* ts    = (const float*)d_in[1];
    const float* eps   = (const float*)d_in[2];
    const float* i2h_w = (const float*)d_in[3];
    const float* i2h_b = (const float*)d_in[4];
    const float* h2o_w = (const float*)d_in[5];
    const float* h2o_b = (const float*)d_in[6];
    const float* f1_w  = (const float*)d_in[7];
    const float* f1_b  = (const float*)d_in[8];
    const float* f2_w  = (const float*)d_in[9];
    const float* f2_b  = (const float*)d_in[10];
    const float* f3_w  = (const float*)d_in[11];
    const float* f3_b  = (const float*)d_in[12];
    const float* d1_w  = (const float*)d_in[13];
    const float* d1_b  = (const float*)d_in[14];
    const float* d2_w  = (const float*)d_in[15];
    const float* d2_b  = (const float*)d_in[16];
    float* out = (float*)d_out;

    // 4096 warps, 4 per block
    rnn_kernel<<<NB / 4, 128>>>(trajs, eps, i2h_w, i2h_b, h2o_w, h2o_b, out);
    // 8 lanes per batch -> 32768 threads
    ode_kernel<<<(NB * 8) / 128, 128>>>(ts, f1_w, f1_b, f2_w, f2_b, f3_w, f3_b);
    // one thread per (b,t)
    dec_kernel<<<(NB * NT) / 256, 256>>>(d1_w, d1_b, d2_w, d2_b, out);
}

// round 3
// speedup vs baseline: 1.6135x; 1.6135x over previous
#include <cuda_runtime.h>
#include <math.h>

#define NB 4096
#define NT 512
#define OBS 2
#define LAT 4
#define NH 20
#define RNNH 25

// scratch: pred_z[b][t][4]
__device__ float g_pred_z[(size_t)NB * NT * LAT];

static __device__ __forceinline__ float tanh_fast(float x) {
    float r;
    asm("tanh.approx.f32 %0, %1;" : "=f"(r) : "f"(x));
    return r;
}
static __device__ __forceinline__ float elu_fast(float x) {
    return x > 0.f ? x : (__expf(x) - 1.f);
}

// ---------------- RNN: one warp per batch, smem h-exchange ----------------
__global__ __launch_bounds__(128) void rnn_kernel(
    const float* __restrict__ trajs,   // (B,T,2)
    const float* __restrict__ eps,     // (B,4)
    const float* __restrict__ i2h_w,   // (27,25)
    const float* __restrict__ i2h_b,   // (25)
    const float* __restrict__ h2o_w,   // (25,8)
    const float* __restrict__ h2o_b,   // (8)
    float* __restrict__ out)
{
    __shared__ __align__(16) float hb[4][2][28];
    int w    = threadIdx.x >> 5;
    int lane = threadIdx.x & 31;
    int b    = blockIdx.x * 4 + w;
    int jc   = (lane < RNNH) ? lane : 0;

    // zero both buffers (incl. padding 25..27)
    if (lane < 28) { hb[w][0][lane] = 0.f; hb[w][1][lane] = 0.f; }
    __syncwarp();

    float W[OBS + RNNH];
#pragma unroll
    for (int r = 0; r < OBS + RNNH; r++) W[r] = __ldg(&i2h_w[r * RNNH + jc]);
    float bj = __ldg(&i2h_b[jc]);

    const float2* xb = (const float2*)(trajs + (size_t)b * NT * OBS);
    float h = 0.f;
    float2 x = __ldg(&xb[NT - 1]);

    for (int t = NT - 1; t >= 0; --t) {
        int pb = t & 1;
        if (lane < RNNH) hb[w][pb][lane] = h;
        float2 xn;
        if (t > 0) xn = __ldg(&xb[t - 1]);
        __syncwarp();
        // gather all 25 h values (padded to 28) via 7 LDS.128 broadcasts
        float hs[28];
        const float4* hv = (const float4*)hb[w][pb];
#pragma unroll
        for (int q = 0; q < 7; q++) ((float4*)hs)[q] = hv[q];
        // tree accumulation: 4 partials
        float a0 = fmaf(x.x, W[0], bj);
        float a1 = x.y * W[1];
        float a2 = 0.f, a3 = 0.f;
#pragma unroll
        for (int k = 0; k < RNNH; k += 4) {
            a0 = fmaf(hs[k], W[2 + k], a0);
            if (k + 1 < RNNH) a1 = fmaf(hs[k + 1], W[3 + k], a1);
            if (k + 2 < RNNH) a2 = fmaf(hs[k + 2], W[4 + k], a2);
            if (k + 3 < RNNH) a3 = fmaf(hs[k + 3], W[5 + k], a3);
        }
        float acc = (a0 + a1) + (a2 + a3);
        h = (lane < RNNH) ? tanh_fast(acc) : 0.f;
        x = xn;
    }

    // out8 = h_last @ h2o_w + h2o_b  (h = 0 for lanes >= 25)
    float p[2 * LAT];
#pragma unroll
    for (int i = 0; i < 2 * LAT; i++) p[i] = h * __ldg(&h2o_w[jc * (2 * LAT) + i]);
#pragma unroll
    for (int off = 16; off >= 1; off >>= 1) {
#pragma unroll
        for (int i = 0; i < 2 * LAT; i++)
            p[i] += __shfl_xor_sync(0xffffffffu, p[i], off);
    }

    if (lane == 0) {
        const size_t PX = (size_t)NB * NT * OBS;
        float z0v[LAT];
#pragma unroll
        for (int i = 0; i < LAT; i++) {
            float mean = p[i] + __ldg(&h2o_b[i]);
            float lv   = p[LAT + i] + __ldg(&h2o_b[LAT + i]);
            float z    = __ldg(&eps[b * LAT + i]) * expf(0.5f * lv) + mean;
            z0v[i] = z;
            out[PX + (size_t)b * LAT + i]                        = z;
            out[PX + (size_t)NB * LAT + (size_t)b * LAT + i]     = mean;
            out[PX + 2 * (size_t)NB * LAT + (size_t)b * LAT + i] = lv;
        }
        *(float4*)(g_pred_z + (size_t)b * NT * LAT) =
            make_float4(z0v[0], z0v[1], z0v[2], z0v[3]);
    }
}

// ---------------- ODE: 8 lanes per batch, smem u-exchange ----------------
__global__ __launch_bounds__(128) void ode_kernel(
    const float* __restrict__ ts,
    const float* __restrict__ f1_w, const float* __restrict__ f1_b,   // (4,20),(20)
    const float* __restrict__ f2_w, const float* __restrict__ f2_b,   // (20,20),(20)
    const float* __restrict__ f3_w, const float* __restrict__ f3_b)   // (20,4),(4)
{
    __shared__ float dts[NT];
    __shared__ __align__(16) float uex[16][2][24];

    int tid = threadIdx.x;
    for (int i = tid; i < NT - 1; i += 128) dts[i] = __ldg(&ts[i + 1]) - __ldg(&ts[i]);

    int g = tid >> 3;
    int s = tid & 7;
    int b = blockIdx.x * 16 + g;

    int jm[3]; bool vm[3];
#pragma unroll
    for (int m = 0; m < 3; m++) {
        int j = s + 8 * m;
        vm[m] = (j < NH);
        jm[m] = vm[m] ? j : 0;
    }

    float W1[LAT][3], W2[NH][3], W3[3][LAT], b1[3], b2[3], b3[LAT];
#pragma unroll
    for (int m = 0; m < 3; m++) {
#pragma unroll
        for (int i = 0; i < LAT; i++) W1[i][m] = __ldg(&f1_w[i * NH + jm[m]]);
#pragma unroll
        for (int k = 0; k < NH; k++)  W2[k][m] = __ldg(&f2_w[k * NH + jm[m]]);
#pragma unroll
        for (int i = 0; i < LAT; i++) W3[m][i] = __ldg(&f3_w[jm[m] * LAT + i]);
        b1[m] = __ldg(&f1_b[jm[m]]);
        b2[m] = __ldg(&f2_b[jm[m]]);
    }
#pragma unroll
    for (int i = 0; i < LAT; i++) b3[i] = __ldg(&f3_b[i]);

    __syncthreads();

    // f(z) -> kout, replicated across the 8 lanes of the group
    auto feval = [&](const float zin[LAT], float kout[LAT], int pb) {
        // layer 1: 3 slots
        float u0[3];
#pragma unroll
        for (int m = 0; m < 3; m++) {
            float a = fmaf(zin[0], W1[0][m], b1[m]);
            float c = zin[1] * W1[1][m];
            a = fmaf(zin[2], W1[2][m], a);
            c = fmaf(zin[3], W1[3][m], c);
            a += c;
            u0[m] = vm[m] ? elu_fast(a) : 0.f;
        }
        // exchange: 3 STS, sync, 5 LDS.128
        uex[g][pb][s]      = u0[0];
        uex[g][pb][s + 8]  = u0[1];
        uex[g][pb][s + 16] = u0[2];
        __syncwarp();
        float us[20];
        const float4* uv = (const float4*)uex[g][pb];
#pragma unroll
        for (int q = 0; q < 5; q++) ((float4*)us)[q] = uv[q];
        // layer 2: 3 slots x 20, two partial accumulators each
        float u2[3];
#pragma unroll
        for (int m = 0; m < 3; m++) {
            float aa = b2[m], bb = 0.f;
#pragma unroll
            for (int k = 0; k < NH; k += 2) {
                aa = fmaf(us[k],     W2[k][m],     aa);
                bb = fmaf(us[k + 1], W2[k + 1][m], bb);
            }
            float a = aa + bb;
            u2[m] = vm[m] ? elu_fast(a) : 0.f;
        }
        // layer 3: partials then width-8 butterfly
        float p[LAT];
#pragma unroll
        for (int i = 0; i < LAT; i++) {
            float q0 = u2[0] * W3[0][i];
            float q1 = fmaf(u2[1], W3[1][i], q0);
            p[i] = fmaf(u2[2], W3[2][i], q1);
        }
#pragma unroll
        for (int off = 4; off >= 1; off >>= 1) {
#pragma unroll
            for (int i = 0; i < LAT; i++)
                p[i] += __shfl_xor_sync(0xffffffffu, p[i], off, 8);
        }
#pragma unroll
        for (int i = 0; i < LAT; i++) kout[i] = p[i] + b3[i];
    };

    float z[LAT];
    {
        float4 zz = *(const float4*)(g_pred_z + (size_t)b * NT * LAT);
        z[0] = zz.x; z[1] = zz.y; z[2] = zz.z; z[3] = zz.w;
    }

    for (int t = 0; t < NT - 1; ++t) {
        float dt = dts[t];
        float k1[LAT], k2[LAT], k3[LAT], k4[LAT], zt[LAT];
        feval(z, k1, 0);
        float hdt = 0.5f * dt;
#pragma unroll
        for (int i = 0; i < LAT; i++) zt[i] = fmaf(hdt, k1[i], z[i]);
        feval(zt, k2, 1);
#pragma unroll
        for (int i = 0; i < LAT; i++) zt[i] = fmaf(hdt, k2[i], z[i]);
        feval(zt, k3, 0);
#pragma unroll
        for (int i = 0; i < LAT; i++) zt[i] = fmaf(dt, k3[i], z[i]);
        feval(zt, k4, 1);
        float c = dt * (1.f / 6.f);
#pragma unroll
        for (int i = 0; i < LAT; i++)
            z[i] = fmaf(c, (k1[i] + k4[i]) + 2.f * (k2[i] + k3[i]), z[i]);
        if (s == 0) {
            *(float4*)(g_pred_z + ((size_t)b * NT + t + 1) * LAT) =
                make_float4(z[0], z[1], z[2], z[3]);
        }
    }
}

// ---------------- Decoder: 4 elems per thread, weights in smem ----------------
__global__ __launch_bounds__(256) void dec_kernel(
    const float* __restrict__ d1_w, const float* __restrict__ d1_b,  // (4,20),(20)
    const float* __restrict__ d2_w, const float* __restrict__ d2_b,  // (20,2),(2)
    float* __restrict__ out)
{
    __shared__ float w1s[80], b1s[20], w2s[40], b2s[2];
    int tid = threadIdx.x;
    if (tid < 80)       w1s[tid] = __ldg(&d1_w[tid]);
    else if (tid < 100) b1s[tid - 80] = __ldg(&d1_b[tid - 80]);
    else if (tid < 140) w2s[tid - 100] = __ldg(&d2_w[tid - 100]);
    else if (tid < 142) b2s[tid - 140] = __ldg(&d2_b[tid - 140]);
    __syncthreads();

    int e0 = (blockIdx.x * 256 + tid) * 4;   // 4 consecutive (b,t) elements
    float4 zv[4];
#pragma unroll
    for (int q = 0; q < 4; q++) zv[q] = *(const float4*)(g_pred_z + (size_t)(e0 + q) * LAT);

    float o0[4], o1[4];
#pragma unroll
    for (int q = 0; q < 4; q++) { o0[q] = b2s[0]; o1[q] = b2s[1]; }

#pragma unroll
    for (int j = 0; j < NH; j++) {
        float w10 = w1s[j], w11 = w1s[20 + j], w12 = w1s[40 + j], w13 = w1s[60 + j];
        float bb = b1s[j];
        float w20 = w2s[2 * j], w21 = w2s[2 * j + 1];
#pragma unroll
        for (int q = 0; q < 4; q++) {
            float hh = fmaf(zv[q].x, w10, bb);
            float h2 = zv[q].y * w11;
            hh = fmaf(zv[q].z, w12, hh);
            h2 = fmaf(zv[q].w, w13, h2);
            hh = fmaxf(hh + h2, 0.f);
            o0[q] = fmaf(hh, w20, o0[q]);
            o1[q] = fmaf(hh, w21, o1[q]);
        }
    }
    float4* op = (float4*)(out + (size_t)e0 * OBS);
    op[0] = make_float4(o0[0], o1[0], o0[1], o1[1]);
    op[1] = make_float4(o0[2], o1[2], o0[3], o1[3]);
}

extern "C" void kernel_launch(void* const* d_in, const int* in_sizes, int n_in,
                              void* d_out, int out_size)
{
    const float* trajs = (const float*)d_in[0];
    const float* ts    = (const float*)d_in[1];
    const float* eps   = (const float*)d_in[2];
    const float* i2h_w = (const float*)d_in[3];
    const float* i2h_b = (const float*)d_in[4];
    const float* h2o_w = (const float*)d_in[5];
    const float* h2o_b = (const float*)d_in[6];
    const float* f1_w  = (const float*)d_in[7];
    const float* f1_b  = (const float*)d_in[8];
    const float* f2_w  = (const float*)d_in[9];
    const float* f2_b  = (const float*)d_in[10];
    const float* f3_w  = (const float*)d_in[11];
    const float* f3_b  = (const float*)d_in[12];
    const float* d1_w  = (const float*)d_in[13];
    const float* d1_b  = (const float*)d_in[14];
    const float* d2_w  = (const float*)d_in[15];
    const float* d2_b  = (const float*)d_in[16];
    float* out = (float*)d_out;

    rnn_kernel<<<NB / 4, 128>>>(trajs, eps, i2h_w, i2h_b, h2o_w, h2o_b, out);
    ode_kernel<<<(NB * 8) / 128, 128>>>(ts, f1_w, f1_b, f2_w, f2_b, f3_w, f3_b);
    dec_kernel<<<(NB * NT) / (256 * 4), 256>>>(d1_w, d1_b, d2_w, d2_b, out);
}